// round 1
// baseline (speedup 1.0000x reference)
#include <cuda_runtime.h>
#include <cstdint>
#include <algorithm>

// ---------------------------------------------------------------------------
// Problem constants
// ---------------------------------------------------------------------------
#define BATCH   256
#define FDIM    128      // feature dim
#define EDIM    128      // encoder dim
#define DDIM    64       // output dim
#define MAXDEG  64
#define NN1     25       // neighbors at level 0 sampling (t=1)
#define NN0     10       // neighbors at level 1 sampling (t=0)
#define ROWS1   (BATCH * 2 * NN1)     // 12800 per set
#define ROWS2   (ROWS1 * 2 * NN0)     // 256000 per set
#define ROWS_BIG (2 * ROWS1)          // 25600 (both sets)
#define KDIM    384                   // 3 * 128

// ---------------------------------------------------------------------------
// Static device scratch (no cudaMalloc allowed)
// ---------------------------------------------------------------------------
__device__ int   g_lvl1[2][ROWS1];
__device__ int   g_lvl2[2][ROWS2];
__device__ float g_aggBig[(size_t)ROWS_BIG * KDIM];   // 39.3 MB
__device__ float g_h11[(size_t)ROWS_BIG * EDIM];      // 13.1 MB
__device__ float g_agg0[2 * BATCH * KDIM];
__device__ float g_h10[2 * BATCH * EDIM];
__device__ float g_aggL1[2 * BATCH * KDIM];
__device__ float g_hhead[2 * BATCH * EDIM];

// Column-index bundle computed on host (exact JAX threefry reproduction)
struct ColsAll {
    int out0[2][NN1];
    int in0[2][NN1];
    int out1[2][NN0];
    int in1[2][NN0];
};

// ---------------------------------------------------------------------------
// Kernels
// ---------------------------------------------------------------------------
__global__ void build_lvl1(const int* __restrict__ nodes1,
                           const int* __restrict__ nodes2,
                           const int* __restrict__ nbr_out,
                           const int* __restrict__ nbr_in,
                           ColsAll cols) {
    int tid = blockIdx.x * blockDim.x + threadIdx.x;
    const int total = 2 * ROWS1;
    if (tid >= total) return;
    int set = tid / ROWS1;
    int rem = tid - set * ROWS1;
    int i = rem / (2 * NN1);
    int j = rem - i * (2 * NN1);
    int node = (set ? nodes2 : nodes1)[i];
    int col;
    const int* nbr;
    if (j < NN1) { col = cols.out0[set][j];        nbr = nbr_out; }
    else         { col = cols.in0[set][j - NN1];   nbr = nbr_in;  }
    g_lvl1[set][rem] = nbr[(size_t)node * MAXDEG + col];
}

__global__ void build_lvl2(const int* __restrict__ nbr_out,
                           const int* __restrict__ nbr_in,
                           ColsAll cols) {
    int tid = blockIdx.x * blockDim.x + threadIdx.x;
    const int total = 2 * ROWS2;
    if (tid >= total) return;
    int set = tid / ROWS2;
    int rem = tid - set * ROWS2;
    int r = rem / (2 * NN0);
    int j = rem - r * (2 * NN0);
    int parent = g_lvl1[set][r];
    int col;
    const int* nbr;
    if (j < NN0) { col = cols.out1[set][j];        nbr = nbr_out; }
    else         { col = cols.in1[set][j - NN0];   nbr = nbr_in;  }
    g_lvl2[set][rem] = nbr[(size_t)parent * MAXDEG + col];
}

// Gather + mean for the big (hop=1, layer 0) aggregation: 25600 rows of 384
__global__ void agg_big(const float* __restrict__ feat) {
    int r = blockIdx.x;          // 0..ROWS_BIG-1
    int d = threadIdx.x;         // 0..127
    int set = r / ROWS1;
    int i = r - set * ROWS1;
    int self = g_lvl1[set][i];
    const int* l2 = &g_lvl2[set][i * 2 * NN0];
    float s = feat[(size_t)self * FDIM + d];
    float so = 0.f, si = 0.f;
#pragma unroll
    for (int j = 0; j < NN0; j++)       so += feat[(size_t)l2[j] * FDIM + d];
#pragma unroll
    for (int j = NN0; j < 2 * NN0; j++) si += feat[(size_t)l2[j] * FDIM + d];
    float* a = &g_aggBig[(size_t)r * KDIM];
    a[d]       = s;
    a[128 + d] = so / (float)NN0;
    a[256 + d] = si / (float)NN0;
}

// hop=0 layer-0 aggregation: 512 rows
__global__ void agg_hop0(const float* __restrict__ feat,
                         const int* __restrict__ nodes1,
                         const int* __restrict__ nodes2) {
    int r = blockIdx.x;
    int d = threadIdx.x;
    int set = r >> 8;
    int i = r & 255;
    int self = (set ? nodes2 : nodes1)[i];
    const int* l1 = &g_lvl1[set][i * 2 * NN1];
    float so = 0.f, si = 0.f;
#pragma unroll
    for (int j = 0; j < NN1; j++)       so += feat[(size_t)l1[j] * FDIM + d];
#pragma unroll
    for (int j = NN1; j < 2 * NN1; j++) si += feat[(size_t)l1[j] * FDIM + d];
    float* a = &g_agg0[(size_t)r * KDIM];
    a[d]       = feat[(size_t)self * FDIM + d];
    a[128 + d] = so / (float)NN1;
    a[256 + d] = si / (float)NN1;
}

// layer-1 aggregation from h10/h11: 512 rows
__global__ void agg_l1() {
    int r = blockIdx.x;
    int d = threadIdx.x;
    int set = r >> 8;
    int i = r & 255;
    const float* h = &g_h11[(size_t)(set * ROWS1 + i * 2 * NN1) * EDIM];
    float so = 0.f, si = 0.f;
#pragma unroll
    for (int j = 0; j < NN1; j++)       so += h[(size_t)j * EDIM + d];
#pragma unroll
    for (int j = NN1; j < 2 * NN1; j++) si += h[(size_t)j * EDIM + d];
    float* a = &g_aggL1[(size_t)r * KDIM];
    a[d]       = g_h10[(size_t)r * EDIM + d];
    a[128 + d] = so / (float)NN1;
    a[256 + d] = si / (float)NN1;
}

__device__ __forceinline__ float sigmoidf_stable(float x) {
    if (x >= 0.f) {
        return 1.f / (1.f + expf(-x));
    } else {
        float e = expf(x);
        return e / (1.f + e);
    }
}

// C[M,128] = sigmoid(A[M,384] @ W[384,128]); buffer selection by `which`
//   which=0: A=g_aggBig  C=g_h11
//   which=1: A=g_agg0    C=g_h10
//   which=2: A=g_aggL1   C=g_hhead
__global__ void __launch_bounds__(256)
gemm_sig(const float* __restrict__ W, int which, int M) {
    const float* A = (which == 0) ? g_aggBig : (which == 1) ? g_agg0 : g_aggL1;
    float* C = (which == 0) ? g_h11 : (which == 1) ? g_h10 : g_hhead;

    __shared__ float As[16][128];
    __shared__ float Bs[16][128];

    int t  = threadIdx.x;          // 0..255
    int tx = t & 15;               // col group
    int ty = t >> 4;               // row group
    int m0 = blockIdx.x * 128;

    float acc[8][8];
#pragma unroll
    for (int i = 0; i < 8; i++)
#pragma unroll
        for (int j = 0; j < 8; j++) acc[i][j] = 0.f;

    for (int k0 = 0; k0 < KDIM; k0 += 16) {
        // Load A tile 128x16 (transposed into smem)
#pragma unroll
        for (int l = 0; l < 2; l++) {
            int f4 = t * 2 + l;           // 0..511
            int m  = f4 >> 2;
            int kq = (f4 & 3) * 4;
            float4 v = *reinterpret_cast<const float4*>(
                &A[(size_t)(m0 + m) * KDIM + k0 + kq]);
            As[kq + 0][m] = v.x;
            As[kq + 1][m] = v.y;
            As[kq + 2][m] = v.z;
            As[kq + 3][m] = v.w;
        }
        // Load B tile 16x128
#pragma unroll
        for (int l = 0; l < 2; l++) {
            int f4 = t * 2 + l;
            int k  = f4 >> 5;
            int c  = (f4 & 31) * 4;
            *reinterpret_cast<float4*>(&Bs[k][c]) =
                *reinterpret_cast<const float4*>(&W[(size_t)(k0 + k) * EDIM + c]);
        }
        __syncthreads();
#pragma unroll
        for (int k = 0; k < 16; k++) {
            float4 a0 = *reinterpret_cast<const float4*>(&As[k][ty * 8]);
            float4 a1 = *reinterpret_cast<const float4*>(&As[k][ty * 8 + 4]);
            float4 b0 = *reinterpret_cast<const float4*>(&Bs[k][tx * 8]);
            float4 b1 = *reinterpret_cast<const float4*>(&Bs[k][tx * 8 + 4]);
            float a[8] = {a0.x, a0.y, a0.z, a0.w, a1.x, a1.y, a1.z, a1.w};
            float b[8] = {b0.x, b0.y, b0.z, b0.w, b1.x, b1.y, b1.z, b1.w};
#pragma unroll
            for (int i = 0; i < 8; i++)
#pragma unroll
                for (int j = 0; j < 8; j++) acc[i][j] += a[i] * b[j];
        }
        __syncthreads();
    }

#pragma unroll
    for (int i = 0; i < 8; i++) {
        int row = m0 + ty * 8 + i;
#pragma unroll
        for (int j = 0; j < 8; j++) {
            C[(size_t)row * EDIM + tx * 8 + j] = sigmoidf_stable(acc[i][j]);
        }
    }
}

// z[512,64] = g_hhead[512,128] @ Wd[128,64]; scatter into stacked output
__global__ void proj64(const float* __restrict__ Wd, float* __restrict__ out, int head) {
    __shared__ float h[128];
    int r = blockIdx.x;       // 0..511
    int c = threadIdx.x;      // 0..63
    h[c]      = g_hhead[(size_t)r * EDIM + c];
    h[c + 64] = g_hhead[(size_t)r * EDIM + 64 + c];
    __syncthreads();
    float s = 0.f;
#pragma unroll
    for (int k = 0; k < 128; k++) s += h[k] * Wd[k * DDIM + c];
    int set = r >> 8;
    int i = r & 255;
    out[((size_t)(set * 3 + head) * BATCH + i) * DDIM + c] = s;
}

// ---------------------------------------------------------------------------
// Host-side JAX threefry reproduction (partitionable mode, JAX >= 0.4.36)
// ---------------------------------------------------------------------------
namespace tfry {

static inline uint32_t rotl32(uint32_t x, int d) { return (x << d) | (x >> (32 - d)); }

struct Key { uint32_t a, b; };

static Key threefry2x32(Key k, uint32_t x0, uint32_t x1) {
    uint32_t ks0 = k.a, ks1 = k.b, ks2 = k.a ^ k.b ^ 0x1BD11BDAu;
    x0 += ks0; x1 += ks1;
    static const int R0[4] = {13, 15, 26, 6};
    static const int R1[4] = {17, 29, 16, 24};
    auto rounds4 = [&](const int* R) {
        for (int i = 0; i < 4; i++) { x0 += x1; x1 = rotl32(x1, R[i]); x1 ^= x0; }
    };
    rounds4(R0); x0 += ks1; x1 += ks2 + 1u;
    rounds4(R1); x0 += ks2; x1 += ks0 + 2u;
    rounds4(R0); x0 += ks0; x1 += ks1 + 3u;
    rounds4(R1); x0 += ks1; x1 += ks2 + 4u;
    rounds4(R0); x0 += ks2; x1 += ks0 + 5u;
    return Key{x0, x1};
}

// foldlike split: keys[i] = threefry(key, (hi(i)=0, lo(i)=i)) for small i
static Key fold(Key k, uint32_t i) { return threefry2x32(k, 0u, i); }

// jax.random.permutation(key, 64)[:n]  (one shuffle round for size 64)
static void perm64_prefix(Key key, int n, int* out) {
    Key subkey = fold(key, 1);             // key, subkey = split(key) -> keys[1]
    uint32_t bits[64];
    int idx[64];
    for (int i = 0; i < 64; i++) {
        Key r = threefry2x32(subkey, 0u, (uint32_t)i);
        bits[i] = r.a ^ r.b;               // 32-bit partitionable random_bits
        idx[i] = i;
    }
    std::stable_sort(idx, idx + 64,
                     [&](int x, int y) { return bits[x] < bits[y]; });
    for (int j = 0; j < n; j++) out[j] = idx[j];
}

}  // namespace tfry

// ---------------------------------------------------------------------------
// kernel_launch
// ---------------------------------------------------------------------------
extern "C" void kernel_launch(void* const* d_in, const int* in_sizes, int n_in,
                              void* d_out, int out_size) {
    const int*   nodes1  = (const int*)d_in[0];
    const int*   nodes2  = (const int*)d_in[1];
    const int*   nbr_out = (const int*)d_in[2];
    const int*   nbr_in  = (const int*)d_in[3];
    const float* feat    = (const float*)d_in[4];
    const float* W_in    = (const float*)d_in[5];
    const float* W_mean  = (const float*)d_in[6];
    const float* W_std   = (const float*)d_in[7];
    const float* W_pi    = (const float*)d_in[8];
    // d_in[9] = W_ag, d_in[10] = W_ad (unused by the reference forward)
    const float* Wd_mean = (const float*)d_in[11];
    const float* Wd_std  = (const float*)d_in[12];
    const float* Wd_pi   = (const float*)d_in[13];
    float* out = (float*)d_out;

    // --- host threefry: reproduce sampling column indices exactly ---
    ColsAll cols;
    tfry::Key root{0u, 42u};                        // jax.random.key(42)
    tfry::Key kset[2] = {tfry::fold(root, 0), tfry::fold(root, 1)};  // k1, k2
    for (int set = 0; set < 2; set++) {
        tfry::Key key = kset[set];
        // k = 0 (t = 1, n = 25)
        {
            tfry::Key nk = tfry::fold(key, 0);
            tfry::Key p1 = tfry::fold(key, 1);
            tfry::Key p2 = tfry::fold(key, 2);
            tfry::perm64_prefix(p1, NN1, cols.out0[set]);
            tfry::perm64_prefix(p2, NN1, cols.in0[set]);
            key = nk;
        }
        // k = 1 (t = 0, n = 10)
        {
            tfry::Key p1 = tfry::fold(key, 1);
            tfry::Key p2 = tfry::fold(key, 2);
            tfry::perm64_prefix(p1, NN0, cols.out1[set]);
            tfry::perm64_prefix(p2, NN0, cols.in1[set]);
        }
    }

    // --- pipeline ---
    build_lvl1<<<(2 * ROWS1 + 255) / 256, 256>>>(nodes1, nodes2, nbr_out, nbr_in, cols);
    build_lvl2<<<(2 * ROWS2 + 255) / 256, 256>>>(nbr_out, nbr_in, cols);

    agg_big<<<ROWS_BIG, 128>>>(feat);
    gemm_sig<<<ROWS_BIG / 128, 256>>>(W_in, 0, ROWS_BIG);   // -> g_h11

    agg_hop0<<<2 * BATCH, 128>>>(feat, nodes1, nodes2);
    gemm_sig<<<(2 * BATCH) / 128, 256>>>(W_in, 1, 2 * BATCH);  // -> g_h10

    agg_l1<<<2 * BATCH, 128>>>();                               // -> g_aggL1

    const float* Wh[3]  = {W_mean, W_std, W_pi};
    const float* Wdh[3] = {Wd_mean, Wd_std, Wd_pi};
    for (int head = 0; head < 3; head++) {
        gemm_sig<<<(2 * BATCH) / 128, 256>>>(Wh[head], 2, 2 * BATCH);  // -> g_hhead
        proj64<<<2 * BATCH, 64>>>(Wdh[head], out, head);
    }
}

// round 2
// speedup vs baseline: 1.6064x; 1.6064x over previous
#include <cuda_runtime.h>
#include <cstdint>
#include <algorithm>

// ---------------------------------------------------------------------------
// Problem constants
// ---------------------------------------------------------------------------
#define BATCH   256
#define FDIM    128
#define EDIM    128
#define DDIM    64
#define MAXDEG  64
#define NN1     25
#define NN0     10
#define ROWS1   (BATCH * 2 * NN1)     // 12800 per set
#define ROWS2   (ROWS1 * 2 * NN0)     // 256000 per set
#define ROWS_BIG (2 * ROWS1)          // 25600
#define KDIM    384

#define RPB     64                    // rows per block in fused_l0
#define SM_A    (RPB * KDIM)          // 24576 floats
#define SM_B    (2 * 8 * EDIM)        // 2048 floats
#define SMEM_FUSED ((SM_A + SM_B) * 4)  // 106496 B

// ---------------------------------------------------------------------------
// Static device scratch
// ---------------------------------------------------------------------------
__device__ int   g_lvl1[2][ROWS1];
__device__ int   g_lvl2[2][ROWS2];
__device__ float g_h11[(size_t)ROWS_BIG * EDIM];      // 13.1 MB
__device__ float g_agg0[2 * BATCH * KDIM];
__device__ float g_h10[2 * BATCH * EDIM];
__device__ float g_aggL1[2 * BATCH * KDIM];
__device__ float g_hhead3[3][2 * BATCH * EDIM];

struct ColsAll {
    int out0[2][NN1];
    int in0[2][NN1];
    int out1[2][NN0];
    int in1[2][NN0];
};

// ---------------------------------------------------------------------------
// Sampling index kernels
// ---------------------------------------------------------------------------
__global__ void build_lvl1(const int* __restrict__ nodes1,
                           const int* __restrict__ nodes2,
                           const int* __restrict__ nbr_out,
                           const int* __restrict__ nbr_in,
                           ColsAll cols) {
    int tid = blockIdx.x * blockDim.x + threadIdx.x;
    const int total = 2 * ROWS1;
    if (tid >= total) return;
    int set = tid / ROWS1;
    int rem = tid - set * ROWS1;
    int i = rem / (2 * NN1);
    int j = rem - i * (2 * NN1);
    int node = (set ? nodes2 : nodes1)[i];
    int col;
    const int* nbr;
    if (j < NN1) { col = cols.out0[set][j];        nbr = nbr_out; }
    else         { col = cols.in0[set][j - NN1];   nbr = nbr_in;  }
    g_lvl1[set][rem] = nbr[(size_t)node * MAXDEG + col];
}

__global__ void build_lvl2(const int* __restrict__ nbr_out,
                           const int* __restrict__ nbr_in,
                           ColsAll cols) {
    int tid = blockIdx.x * blockDim.x + threadIdx.x;
    const int total = 2 * ROWS2;
    if (tid >= total) return;
    int set = tid / ROWS2;
    int rem = tid - set * ROWS2;
    int r = rem / (2 * NN0);
    int j = rem - r * (2 * NN0);
    int parent = g_lvl1[set][r];
    int col;
    const int* nbr;
    if (j < NN0) { col = cols.out1[set][j];        nbr = nbr_out; }
    else         { col = cols.in1[set][j - NN0];   nbr = nbr_in;  }
    g_lvl2[set][rem] = nbr[(size_t)parent * MAXDEG + col];
}

// ---------------------------------------------------------------------------
// Fused level-0 big path: gather + mean -> smem A[64][384], then
// sigmoid(A @ W_in[384,128]) -> g_h11.  Grid = 400, block = 256.
// ---------------------------------------------------------------------------
__device__ __forceinline__ float sigmoidf_stable(float x) {
    if (x >= 0.f) {
        return 1.f / (1.f + expf(-x));
    } else {
        float e = expf(x);
        return e / (1.f + e);
    }
}

__global__ void __launch_bounds__(256, 2)
fused_l0(const float* __restrict__ feat, const float* __restrict__ W) {
    extern __shared__ float sm[];
    float* As = sm;           // [RPB][KDIM] row-major
    float* Bs = sm + SM_A;    // [2][8][EDIM]

    const int t    = threadIdx.x;
    const int lane = t & 31;
    const int w    = t >> 5;            // warp 0..7
    const int r0   = blockIdx.x * RPB;

    // ---- Phase 1: gather + mean into smem ----
    const float4* feat4 = reinterpret_cast<const float4*>(feat);
    const float inv = 1.0f / (float)NN0;
#pragma unroll
    for (int rr = 0; rr < RPB / 8; rr++) {
        int r = w * (RPB / 8) + rr;
        int R = r0 + r;
        int set = (R >= ROWS1) ? 1 : 0;
        int i = R - set * ROWS1;
        int self = g_lvl1[set][i];
        const int* l2 = &g_lvl2[set][i * 2 * NN0];

        float4 vs = feat4[(size_t)self * 32 + lane];
        float4 ao = make_float4(0.f, 0.f, 0.f, 0.f);
        float4 ai = make_float4(0.f, 0.f, 0.f, 0.f);
#pragma unroll
        for (int j = 0; j < NN0; j++) {
            float4 v = feat4[(size_t)l2[j] * 32 + lane];
            ao.x += v.x; ao.y += v.y; ao.z += v.z; ao.w += v.w;
        }
#pragma unroll
        for (int j = NN0; j < 2 * NN0; j++) {
            float4 v = feat4[(size_t)l2[j] * 32 + lane];
            ai.x += v.x; ai.y += v.y; ai.z += v.z; ai.w += v.w;
        }
        float* arow = &As[r * KDIM];
        *reinterpret_cast<float4*>(&arow[lane * 4]) = vs;
        float4 mo = make_float4(ao.x * inv, ao.y * inv, ao.z * inv, ao.w * inv);
        float4 mi = make_float4(ai.x * inv, ai.y * inv, ai.z * inv, ai.w * inv);
        *reinterpret_cast<float4*>(&arow[128 + lane * 4]) = mo;
        *reinterpret_cast<float4*>(&arow[256 + lane * 4]) = mi;
    }

    // ---- Phase 2: GEMM + sigmoid ----
    // thread (ty=w, tx=lane): rows ty*8..ty*8+7, cols tx*4..tx*4+3
    const int ty = w;
    const int tx = lane;
    const int kk0 = t >> 5;         // panel row this thread loads (0..7)
    const int c0  = (t & 31) * 4;   // panel col

    float acc[8][4];
#pragma unroll
    for (int i = 0; i < 8; i++)
#pragma unroll
        for (int q = 0; q < 4; q++) acc[i][q] = 0.f;

    // preload first W panel into cur register
    float4 cur = *reinterpret_cast<const float4*>(&W[(size_t)kk0 * EDIM + c0]);
    __syncthreads();   // As complete

    const int NPANEL = KDIM / 8;   // 48
    for (int p = 0; p < NPANEL; p++) {
        int buf = p & 1;
        // store current panel, prefetch next
        *reinterpret_cast<float4*>(&Bs[(buf * 8 + kk0) * EDIM + c0]) = cur;
        if (p + 1 < NPANEL) {
            cur = *reinterpret_cast<const float4*>(
                &W[(size_t)((p + 1) * 8 + kk0) * EDIM + c0]);
        }
        __syncthreads();   // panel visible

        const float* arow0 = &As[(ty * 8) * KDIM + p * 8];
#pragma unroll
        for (int kk = 0; kk < 8; kk++) {
            float4 bv = *reinterpret_cast<const float4*>(
                &Bs[(buf * 8 + kk) * EDIM + tx * 4]);
            float a0 = arow0[0 * KDIM + kk];
            float a1 = arow0[1 * KDIM + kk];
            float a2 = arow0[2 * KDIM + kk];
            float a3 = arow0[3 * KDIM + kk];
            float a4 = arow0[4 * KDIM + kk];
            float a5 = arow0[5 * KDIM + kk];
            float a6 = arow0[6 * KDIM + kk];
            float a7 = arow0[7 * KDIM + kk];
            acc[0][0] += a0 * bv.x; acc[0][1] += a0 * bv.y; acc[0][2] += a0 * bv.z; acc[0][3] += a0 * bv.w;
            acc[1][0] += a1 * bv.x; acc[1][1] += a1 * bv.y; acc[1][2] += a1 * bv.z; acc[1][3] += a1 * bv.w;
            acc[2][0] += a2 * bv.x; acc[2][1] += a2 * bv.y; acc[2][2] += a2 * bv.z; acc[2][3] += a2 * bv.w;
            acc[3][0] += a3 * bv.x; acc[3][1] += a3 * bv.y; acc[3][2] += a3 * bv.z; acc[3][3] += a3 * bv.w;
            acc[4][0] += a4 * bv.x; acc[4][1] += a4 * bv.y; acc[4][2] += a4 * bv.z; acc[4][3] += a4 * bv.w;
            acc[5][0] += a5 * bv.x; acc[5][1] += a5 * bv.y; acc[5][2] += a5 * bv.z; acc[5][3] += a5 * bv.w;
            acc[6][0] += a6 * bv.x; acc[6][1] += a6 * bv.y; acc[6][2] += a6 * bv.z; acc[6][3] += a6 * bv.w;
            acc[7][0] += a7 * bv.x; acc[7][1] += a7 * bv.y; acc[7][2] += a7 * bv.z; acc[7][3] += a7 * bv.w;
        }
        __syncthreads();   // all reads of this buffer done
    }

#pragma unroll
    for (int i = 0; i < 8; i++) {
        int R = r0 + ty * 8 + i;
        float4 o;
        o.x = sigmoidf_stable(acc[i][0]);
        o.y = sigmoidf_stable(acc[i][1]);
        o.z = sigmoidf_stable(acc[i][2]);
        o.w = sigmoidf_stable(acc[i][3]);
        *reinterpret_cast<float4*>(&g_h11[(size_t)R * EDIM + tx * 4]) = o;
    }
}

// ---------------------------------------------------------------------------
// Small path kernels (512 rows)
// ---------------------------------------------------------------------------
__global__ void agg_hop0(const float* __restrict__ feat,
                         const int* __restrict__ nodes1,
                         const int* __restrict__ nodes2) {
    int r = blockIdx.x;
    int d = threadIdx.x;
    int set = r >> 8;
    int i = r & 255;
    int self = (set ? nodes2 : nodes1)[i];
    const int* l1 = &g_lvl1[set][i * 2 * NN1];
    float so = 0.f, si = 0.f;
#pragma unroll
    for (int j = 0; j < NN1; j++)       so += feat[(size_t)l1[j] * FDIM + d];
#pragma unroll
    for (int j = NN1; j < 2 * NN1; j++) si += feat[(size_t)l1[j] * FDIM + d];
    float* a = &g_agg0[(size_t)r * KDIM];
    a[d]       = feat[(size_t)self * FDIM + d];
    a[128 + d] = so / (float)NN1;
    a[256 + d] = si / (float)NN1;
}

__global__ void agg_l1() {
    int r = blockIdx.x;
    int d = threadIdx.x;
    int set = r >> 8;
    int i = r & 255;
    const float* h = &g_h11[(size_t)(set * ROWS1 + i * 2 * NN1) * EDIM];
    float so = 0.f, si = 0.f;
#pragma unroll
    for (int j = 0; j < NN1; j++)       so += h[(size_t)j * EDIM + d];
#pragma unroll
    for (int j = NN1; j < 2 * NN1; j++) si += h[(size_t)j * EDIM + d];
    float* a = &g_aggL1[(size_t)r * KDIM];
    a[d]       = g_h10[(size_t)r * EDIM + d];
    a[128 + d] = so / (float)NN1;
    a[256 + d] = si / (float)NN1;
}

// Generic small GEMM+sigmoid: C[M,128] = sigmoid(A[M,384] @ W[384,128])
//   mode=1: A=g_agg0  -> C=g_h10              (grid.x=M/128, grid.y=1)
//   mode=2: A=g_aggL1 -> C=g_hhead3[blockIdx.y] with W per head
__global__ void __launch_bounds__(256)
gemm_sig(const float* __restrict__ W0, const float* __restrict__ W1,
         const float* __restrict__ W2, int mode) {
    const float* A = (mode == 1) ? g_agg0 : g_aggL1;
    const float* W = (mode == 1) ? W0
                   : (blockIdx.y == 0 ? W0 : (blockIdx.y == 1 ? W1 : W2));
    float* C = (mode == 1) ? g_h10 : g_hhead3[blockIdx.y];

    __shared__ float As[16][128];
    __shared__ float Bs[16][128];

    int t  = threadIdx.x;
    int tx = t & 15;
    int ty = t >> 4;
    int m0 = blockIdx.x * 128;

    float acc[8][8];
#pragma unroll
    for (int i = 0; i < 8; i++)
#pragma unroll
        for (int j = 0; j < 8; j++) acc[i][j] = 0.f;

    for (int k0 = 0; k0 < KDIM; k0 += 16) {
#pragma unroll
        for (int l = 0; l < 2; l++) {
            int f4 = t * 2 + l;
            int m  = f4 >> 2;
            int kq = (f4 & 3) * 4;
            float4 v = *reinterpret_cast<const float4*>(
                &A[(size_t)(m0 + m) * KDIM + k0 + kq]);
            As[kq + 0][m] = v.x;
            As[kq + 1][m] = v.y;
            As[kq + 2][m] = v.z;
            As[kq + 3][m] = v.w;
        }
#pragma unroll
        for (int l = 0; l < 2; l++) {
            int f4 = t * 2 + l;
            int k  = f4 >> 5;
            int c  = (f4 & 31) * 4;
            *reinterpret_cast<float4*>(&Bs[k][c]) =
                *reinterpret_cast<const float4*>(&W[(size_t)(k0 + k) * EDIM + c]);
        }
        __syncthreads();
#pragma unroll
        for (int k = 0; k < 16; k++) {
            float4 a0 = *reinterpret_cast<const float4*>(&As[k][ty * 8]);
            float4 a1 = *reinterpret_cast<const float4*>(&As[k][ty * 8 + 4]);
            float4 b0 = *reinterpret_cast<const float4*>(&Bs[k][tx * 8]);
            float4 b1 = *reinterpret_cast<const float4*>(&Bs[k][tx * 8 + 4]);
            float a[8] = {a0.x, a0.y, a0.z, a0.w, a1.x, a1.y, a1.z, a1.w};
            float b[8] = {b0.x, b0.y, b0.z, b0.w, b1.x, b1.y, b1.z, b1.w};
#pragma unroll
            for (int i = 0; i < 8; i++)
#pragma unroll
                for (int j = 0; j < 8; j++) acc[i][j] += a[i] * b[j];
        }
        __syncthreads();
    }

#pragma unroll
    for (int i = 0; i < 8; i++) {
        int row = m0 + ty * 8 + i;
#pragma unroll
        for (int j = 0; j < 8; j++) {
            C[(size_t)row * EDIM + tx * 8 + j] = sigmoidf_stable(acc[i][j]);
        }
    }
}

// z[512,64] = g_hhead3[head] @ Wd; scatter into stacked output. grid (512, 3)
__global__ void proj3(const float* __restrict__ Wdm,
                      const float* __restrict__ Wds,
                      const float* __restrict__ Wdp,
                      float* __restrict__ out) {
    __shared__ float h[128];
    int head = blockIdx.y;
    const float* Wd = (head == 0) ? Wdm : (head == 1) ? Wds : Wdp;
    int r = blockIdx.x;
    int c = threadIdx.x;
    const float* H = g_hhead3[head];
    h[c]      = H[(size_t)r * EDIM + c];
    h[c + 64] = H[(size_t)r * EDIM + 64 + c];
    __syncthreads();
    float s = 0.f;
#pragma unroll
    for (int k = 0; k < 128; k++) s += h[k] * Wd[k * DDIM + c];
    int set = r >> 8;
    int i = r & 255;
    out[((size_t)(set * 3 + head) * BATCH + i) * DDIM + c] = s;
}

// ---------------------------------------------------------------------------
// Host-side JAX threefry reproduction (partitionable mode)
// ---------------------------------------------------------------------------
namespace tfry {

static inline uint32_t rotl32(uint32_t x, int d) { return (x << d) | (x >> (32 - d)); }

struct Key { uint32_t a, b; };

static Key threefry2x32(Key k, uint32_t x0, uint32_t x1) {
    uint32_t ks0 = k.a, ks1 = k.b, ks2 = k.a ^ k.b ^ 0x1BD11BDAu;
    x0 += ks0; x1 += ks1;
    static const int R0[4] = {13, 15, 26, 6};
    static const int R1[4] = {17, 29, 16, 24};
    auto rounds4 = [&](const int* R) {
        for (int i = 0; i < 4; i++) { x0 += x1; x1 = rotl32(x1, R[i]); x1 ^= x0; }
    };
    rounds4(R0); x0 += ks1; x1 += ks2 + 1u;
    rounds4(R1); x0 += ks2; x1 += ks0 + 2u;
    rounds4(R0); x0 += ks0; x1 += ks1 + 3u;
    rounds4(R1); x0 += ks1; x1 += ks2 + 4u;
    rounds4(R0); x0 += ks2; x1 += ks0 + 5u;
    return Key{x0, x1};
}

static Key fold(Key k, uint32_t i) { return threefry2x32(k, 0u, i); }

static void perm64_prefix(Key key, int n, int* out) {
    Key subkey = fold(key, 1);
    uint32_t bits[64];
    int idx[64];
    for (int i = 0; i < 64; i++) {
        Key r = threefry2x32(subkey, 0u, (uint32_t)i);
        bits[i] = r.a ^ r.b;
        idx[i] = i;
    }
    std::stable_sort(idx, idx + 64,
                     [&](int x, int y) { return bits[x] < bits[y]; });
    for (int j = 0; j < n; j++) out[j] = idx[j];
}

}  // namespace tfry

// ---------------------------------------------------------------------------
// kernel_launch
// ---------------------------------------------------------------------------
extern "C" void kernel_launch(void* const* d_in, const int* in_sizes, int n_in,
                              void* d_out, int out_size) {
    const int*   nodes1  = (const int*)d_in[0];
    const int*   nodes2  = (const int*)d_in[1];
    const int*   nbr_out = (const int*)d_in[2];
    const int*   nbr_in  = (const int*)d_in[3];
    const float* feat    = (const float*)d_in[4];
    const float* W_in    = (const float*)d_in[5];
    const float* W_mean  = (const float*)d_in[6];
    const float* W_std   = (const float*)d_in[7];
    const float* W_pi    = (const float*)d_in[8];
    const float* Wd_mean = (const float*)d_in[11];
    const float* Wd_std  = (const float*)d_in[12];
    const float* Wd_pi   = (const float*)d_in[13];
    float* out = (float*)d_out;

    cudaFuncSetAttribute(fused_l0, cudaFuncAttributeMaxDynamicSharedMemorySize,
                         SMEM_FUSED);

    // --- host threefry: sampling column indices ---
    ColsAll cols;
    tfry::Key root{0u, 42u};
    tfry::Key kset[2] = {tfry::fold(root, 0), tfry::fold(root, 1)};
    for (int set = 0; set < 2; set++) {
        tfry::Key key = kset[set];
        {
            tfry::Key nk = tfry::fold(key, 0);
            tfry::Key p1 = tfry::fold(key, 1);
            tfry::Key p2 = tfry::fold(key, 2);
            tfry::perm64_prefix(p1, NN1, cols.out0[set]);
            tfry::perm64_prefix(p2, NN1, cols.in0[set]);
            key = nk;
        }
        {
            tfry::Key p1 = tfry::fold(key, 1);
            tfry::Key p2 = tfry::fold(key, 2);
            tfry::perm64_prefix(p1, NN0, cols.out1[set]);
            tfry::perm64_prefix(p2, NN0, cols.in1[set]);
        }
    }

    // --- pipeline ---
    build_lvl1<<<(2 * ROWS1 + 255) / 256, 256>>>(nodes1, nodes2, nbr_out, nbr_in, cols);
    build_lvl2<<<(2 * ROWS2 + 255) / 256, 256>>>(nbr_out, nbr_in, cols);

    fused_l0<<<ROWS_BIG / RPB, 256, SMEM_FUSED>>>(feat, W_in);   // -> g_h11

    agg_hop0<<<2 * BATCH, 128>>>(feat, nodes1, nodes2);
    gemm_sig<<<dim3((2 * BATCH) / 128, 1), 256>>>(W_in, nullptr, nullptr, 1); // -> g_h10

    agg_l1<<<2 * BATCH, 128>>>();                                // -> g_aggL1

    gemm_sig<<<dim3((2 * BATCH) / 128, 3), 256>>>(W_mean, W_std, W_pi, 2); // -> g_hhead3
    proj3<<<dim3(2 * BATCH, 3), 64>>>(Wd_mean, Wd_std, Wd_pi, out);
}

// round 3
// speedup vs baseline: 1.7275x; 1.0754x over previous
#include <cuda_runtime.h>
#include <cstdint>
#include <algorithm>

// ---------------------------------------------------------------------------
// Problem constants
// ---------------------------------------------------------------------------
#define BATCH   256
#define FDIM    128
#define EDIM    128
#define DDIM    64
#define MAXDEG  64
#define NN1     25
#define NN0     10
#define ROWS1   (BATCH * 2 * NN1)     // 12800 per set
#define ROWS2   (ROWS1 * 2 * NN0)     // 256000 per set
#define ROWS_BIG (2 * ROWS1)          // 25600
#define KDIM    384

#define RPB     64                    // rows per block in fused_l0
#define ASTRIDE 388                   // 384 + 4 pad -> conflict-free A-frag LDS
#define SM_A    (RPB * ASTRIDE)       // 24832 floats
#define SM_B    (8 * 128)             // one 8-k panel of W, swizzled
#define SMEM_FUSED ((SM_A + 2 * SM_B) * 4)   // 107520 B

// ---------------------------------------------------------------------------
// Static device scratch
// ---------------------------------------------------------------------------
__device__ int   g_lvl1[2][ROWS1];
__device__ int   g_lvl2[2][ROWS2];
__device__ float g_h11[(size_t)ROWS_BIG * EDIM];      // 13.1 MB
__device__ float g_agg0[2 * BATCH * KDIM];
__device__ float g_h10[2 * BATCH * EDIM];
__device__ float g_aggL1[2 * BATCH * KDIM];
__device__ float g_hhead3[3][2 * BATCH * EDIM];

struct ColsAll {
    int out0[2][NN1];
    int in0[2][NN1];
    int out1[2][NN0];
    int in1[2][NN0];
};

// ---------------------------------------------------------------------------
// Sampling index kernels
// ---------------------------------------------------------------------------
__global__ void build_lvl1(const int* __restrict__ nodes1,
                           const int* __restrict__ nodes2,
                           const int* __restrict__ nbr_out,
                           const int* __restrict__ nbr_in,
                           ColsAll cols) {
    int tid = blockIdx.x * blockDim.x + threadIdx.x;
    const int total = 2 * ROWS1;
    if (tid >= total) return;
    int set = tid / ROWS1;
    int rem = tid - set * ROWS1;
    int i = rem / (2 * NN1);
    int j = rem - i * (2 * NN1);
    int node = (set ? nodes2 : nodes1)[i];
    int col;
    const int* nbr;
    if (j < NN1) { col = cols.out0[set][j];        nbr = nbr_out; }
    else         { col = cols.in0[set][j - NN1];   nbr = nbr_in;  }
    g_lvl1[set][rem] = nbr[(size_t)node * MAXDEG + col];
}

__global__ void build_lvl2(const int* __restrict__ nbr_out,
                           const int* __restrict__ nbr_in,
                           ColsAll cols) {
    int tid = blockIdx.x * blockDim.x + threadIdx.x;
    const int total = 2 * ROWS2;
    if (tid >= total) return;
    int set = tid / ROWS2;
    int rem = tid - set * ROWS2;
    int r = rem / (2 * NN0);
    int j = rem - r * (2 * NN0);
    int parent = g_lvl1[set][r];
    int col;
    const int* nbr;
    if (j < NN0) { col = cols.out1[set][j];        nbr = nbr_out; }
    else         { col = cols.in1[set][j - NN0];   nbr = nbr_in;  }
    g_lvl2[set][rem] = nbr[(size_t)parent * MAXDEG + col];
}

// ---------------------------------------------------------------------------
// Helpers
// ---------------------------------------------------------------------------
__device__ __forceinline__ float sigmoidf_stable(float x) {
    if (x >= 0.f) {
        return 1.f / (1.f + expf(-x));
    } else {
        float e = expf(x);
        return e / (1.f + e);
    }
}

__device__ __forceinline__ unsigned tf32_rna(float x) {
    unsigned r;
    asm("cvt.rna.tf32.f32 %0, %1;" : "=r"(r) : "f"(x));
    return r;
}

__device__ __forceinline__ void mma_tf32(float* c,
                                         unsigned a0, unsigned a1,
                                         unsigned a2, unsigned a3,
                                         unsigned b0, unsigned b1) {
    asm volatile(
        "mma.sync.aligned.m16n8k8.row.col.f32.tf32.tf32.f32 "
        "{%0,%1,%2,%3}, {%4,%5,%6,%7}, {%8,%9}, {%0,%1,%2,%3};"
        : "+f"(c[0]), "+f"(c[1]), "+f"(c[2]), "+f"(c[3])
        : "r"(a0), "r"(a1), "r"(a2), "r"(a3), "r"(b0), "r"(b1));
}

// ---------------------------------------------------------------------------
// Fused level-0 big path: gather+mean -> smem A[64][388], then
// sigmoid(A @ W_in) via 3xTF32 tensor-core MMA -> g_h11.
// Grid = 400, block = 256 (8 warps: 4 row-tiles x 2 col-tiles).
// ---------------------------------------------------------------------------
__global__ void __launch_bounds__(256, 2)
fused_l0(const float* __restrict__ feat, const float* __restrict__ W) {
    extern __shared__ float sm[];
    float* As    = sm;                 // [RPB][ASTRIDE]
    float* Bs_hi = sm + SM_A;          // [8][128] swizzled
    float* Bs_lo = Bs_hi + SM_B;

    const int t    = threadIdx.x;
    const int lane = t & 31;
    const int w    = t >> 5;
    const int r0   = blockIdx.x * RPB;

    // ---- Phase 1: gather + mean into smem ----
    const float4* feat4 = reinterpret_cast<const float4*>(feat);
    const float inv = 1.0f / (float)NN0;
#pragma unroll
    for (int rr = 0; rr < RPB / 8; rr++) {
        int r = w * (RPB / 8) + rr;
        int R = r0 + r;
        int set = (R >= ROWS1) ? 1 : 0;
        int i = R - set * ROWS1;
        int self = g_lvl1[set][i];
        const int* l2 = &g_lvl2[set][i * 2 * NN0];

        float4 vs = feat4[(size_t)self * 32 + lane];
        float4 ao = make_float4(0.f, 0.f, 0.f, 0.f);
        float4 ai = make_float4(0.f, 0.f, 0.f, 0.f);
#pragma unroll
        for (int j = 0; j < NN0; j++) {
            float4 v = feat4[(size_t)l2[j] * 32 + lane];
            ao.x += v.x; ao.y += v.y; ao.z += v.z; ao.w += v.w;
        }
#pragma unroll
        for (int j = NN0; j < 2 * NN0; j++) {
            float4 v = feat4[(size_t)l2[j] * 32 + lane];
            ai.x += v.x; ai.y += v.y; ai.z += v.z; ai.w += v.w;
        }
        float* arow = &As[r * ASTRIDE];
        *reinterpret_cast<float4*>(&arow[lane * 4]) = vs;
        float4 mo = make_float4(ao.x * inv, ao.y * inv, ao.z * inv, ao.w * inv);
        float4 mi = make_float4(ai.x * inv, ai.y * inv, ai.z * inv, ai.w * inv);
        *reinterpret_cast<float4*>(&arow[128 + lane * 4]) = mo;
        *reinterpret_cast<float4*>(&arow[256 + lane * 4]) = mi;
    }

    // ---- Phase 2: 3xTF32 MMA ----
    const int group = lane >> 2;          // 0..7
    const int tid4  = lane & 3;           // 0..3
    const int R0w   = (w & 3) * 16;       // warp row tile within block
    const int C0    = (w >> 2) * 64;      // warp col tile

    float acc[8][4];
#pragma unroll
    for (int j = 0; j < 8; j++)
#pragma unroll
        for (int q = 0; q < 4; q++) acc[j][q] = 0.f;

    // W panel loader indices: this thread loads one float4 of the 8x128 panel
    const int pk = t >> 5;                // panel row 0..7
    const int pn = (t & 31) * 4;          // panel col
    const int sb = pk * 128 + (pn ^ (pk * 8));   // swizzled store base

    float4 wv = *reinterpret_cast<const float4*>(&W[(size_t)pk * EDIM + pn]);

    const int NP = KDIM / 8;   // 48
    for (int p = 0; p < NP; p++) {
        __syncthreads();   // previous panel's consumers done (and As ready at p=0)
        {
            unsigned hx = tf32_rna(wv.x), hy = tf32_rna(wv.y),
                     hz = tf32_rna(wv.z), hw = tf32_rna(wv.w);
            float fhx = __uint_as_float(hx), fhy = __uint_as_float(hy),
                  fhz = __uint_as_float(hz), fhw = __uint_as_float(hw);
            float4 hv = make_float4(fhx, fhy, fhz, fhw);
            float4 lv = make_float4(
                __uint_as_float(tf32_rna(wv.x - fhx)),
                __uint_as_float(tf32_rna(wv.y - fhy)),
                __uint_as_float(tf32_rna(wv.z - fhz)),
                __uint_as_float(tf32_rna(wv.w - fhw)));
            *reinterpret_cast<float4*>(&Bs_hi[sb]) = hv;
            *reinterpret_cast<float4*>(&Bs_lo[sb]) = lv;
        }
        __syncthreads();   // panel visible
        if (p + 1 < NP) {
            wv = *reinterpret_cast<const float4*>(
                &W[(size_t)((p + 1) * 8 + pk) * EDIM + pn]);
        }

        // A fragment (m16 x k8), rows R0w+group / +8, cols p*8 + tid4 / +4
        const float* ar  = &As[(R0w + group) * ASTRIDE + p * 8];
        const float* ar8 = ar + 8 * ASTRIDE;
        float x00 = ar[tid4];        // a0: (g,   k)
        float x10 = ar8[tid4];       // a1: (g+8, k)
        float x01 = ar[tid4 + 4];    // a2: (g,   k+4)
        float x11 = ar8[tid4 + 4];   // a3: (g+8, k+4)
        unsigned ah0 = tf32_rna(x00), ah1 = tf32_rna(x10),
                 ah2 = tf32_rna(x01), ah3 = tf32_rna(x11);
        unsigned al0 = tf32_rna(x00 - __uint_as_float(ah0));
        unsigned al1 = tf32_rna(x10 - __uint_as_float(ah1));
        unsigned al2 = tf32_rna(x01 - __uint_as_float(ah2));
        unsigned al3 = tf32_rna(x11 - __uint_as_float(ah3));

#pragma unroll
        for (int j = 0; j < 8; j++) {
            int nl = C0 + j * 8 + group;
            unsigned bh0 = __float_as_uint(Bs_hi[tid4 * 128 + (nl ^ (tid4 * 8))]);
            unsigned bh1 = __float_as_uint(
                Bs_hi[(tid4 + 4) * 128 + (nl ^ ((tid4 + 4) * 8))]);
            unsigned bl0 = __float_as_uint(Bs_lo[tid4 * 128 + (nl ^ (tid4 * 8))]);
            unsigned bl1 = __float_as_uint(
                Bs_lo[(tid4 + 4) * 128 + (nl ^ ((tid4 + 4) * 8))]);
            mma_tf32(acc[j], ah0, ah1, ah2, ah3, bh0, bh1);
            mma_tf32(acc[j], al0, al1, al2, al3, bh0, bh1);
            mma_tf32(acc[j], ah0, ah1, ah2, ah3, bl0, bl1);
        }
    }

    // ---- Epilogue: sigmoid + store ----
    const int Ra = r0 + R0w + group;
    const int Rb = Ra + 8;
#pragma unroll
    for (int j = 0; j < 8; j++) {
        int col = C0 + j * 8 + 2 * tid4;
        float2 oa, ob;
        oa.x = sigmoidf_stable(acc[j][0]);
        oa.y = sigmoidf_stable(acc[j][1]);
        ob.x = sigmoidf_stable(acc[j][2]);
        ob.y = sigmoidf_stable(acc[j][3]);
        *reinterpret_cast<float2*>(&g_h11[(size_t)Ra * EDIM + col]) = oa;
        *reinterpret_cast<float2*>(&g_h11[(size_t)Rb * EDIM + col]) = ob;
    }
}

// ---------------------------------------------------------------------------
// Small path kernels (512 rows)
// ---------------------------------------------------------------------------
__global__ void agg_hop0(const float* __restrict__ feat,
                         const int* __restrict__ nodes1,
                         const int* __restrict__ nodes2) {
    int r = blockIdx.x;
    int d = threadIdx.x;
    int set = r >> 8;
    int i = r & 255;
    int self = (set ? nodes2 : nodes1)[i];
    const int* l1 = &g_lvl1[set][i * 2 * NN1];
    float so = 0.f, si = 0.f;
#pragma unroll
    for (int j = 0; j < NN1; j++)       so += feat[(size_t)l1[j] * FDIM + d];
#pragma unroll
    for (int j = NN1; j < 2 * NN1; j++) si += feat[(size_t)l1[j] * FDIM + d];
    float* a = &g_agg0[(size_t)r * KDIM];
    a[d]       = feat[(size_t)self * FDIM + d];
    a[128 + d] = so / (float)NN1;
    a[256 + d] = si / (float)NN1;
}

__global__ void agg_l1() {
    int r = blockIdx.x;
    int d = threadIdx.x;
    int set = r >> 8;
    int i = r & 255;
    const float* h = &g_h11[(size_t)(set * ROWS1 + i * 2 * NN1) * EDIM];
    float so = 0.f, si = 0.f;
#pragma unroll
    for (int j = 0; j < NN1; j++)       so += h[(size_t)j * EDIM + d];
#pragma unroll
    for (int j = NN1; j < 2 * NN1; j++) si += h[(size_t)j * EDIM + d];
    float* a = &g_aggL1[(size_t)r * KDIM];
    a[d]       = g_h10[(size_t)r * EDIM + d];
    a[128 + d] = so / (float)NN1;
    a[256 + d] = si / (float)NN1;
}

// Generic small GEMM+sigmoid: C[M,128] = sigmoid(A[M,384] @ W[384,128])
__global__ void __launch_bounds__(256)
gemm_sig(const float* __restrict__ W0, const float* __restrict__ W1,
         const float* __restrict__ W2, int mode) {
    const float* A = (mode == 1) ? g_agg0 : g_aggL1;
    const float* W = (mode == 1) ? W0
                   : (blockIdx.y == 0 ? W0 : (blockIdx.y == 1 ? W1 : W2));
    float* C = (mode == 1) ? g_h10 : g_hhead3[blockIdx.y];

    __shared__ float As[16][128];
    __shared__ float Bs[16][128];

    int t  = threadIdx.x;
    int tx = t & 15;
    int ty = t >> 4;
    int m0 = blockIdx.x * 128;

    float acc[8][8];
#pragma unroll
    for (int i = 0; i < 8; i++)
#pragma unroll
        for (int j = 0; j < 8; j++) acc[i][j] = 0.f;

    for (int k0 = 0; k0 < KDIM; k0 += 16) {
#pragma unroll
        for (int l = 0; l < 2; l++) {
            int f4 = t * 2 + l;
            int m  = f4 >> 2;
            int kq = (f4 & 3) * 4;
            float4 v = *reinterpret_cast<const float4*>(
                &A[(size_t)(m0 + m) * KDIM + k0 + kq]);
            As[kq + 0][m] = v.x;
            As[kq + 1][m] = v.y;
            As[kq + 2][m] = v.z;
            As[kq + 3][m] = v.w;
        }
#pragma unroll
        for (int l = 0; l < 2; l++) {
            int f4 = t * 2 + l;
            int k  = f4 >> 5;
            int c  = (f4 & 31) * 4;
            *reinterpret_cast<float4*>(&Bs[k][c]) =
                *reinterpret_cast<const float4*>(&W[(size_t)(k0 + k) * EDIM + c]);
        }
        __syncthreads();
#pragma unroll
        for (int k = 0; k < 16; k++) {
            float4 a0 = *reinterpret_cast<const float4*>(&As[k][ty * 8]);
            float4 a1 = *reinterpret_cast<const float4*>(&As[k][ty * 8 + 4]);
            float4 b0 = *reinterpret_cast<const float4*>(&Bs[k][tx * 8]);
            float4 b1 = *reinterpret_cast<const float4*>(&Bs[k][tx * 8 + 4]);
            float a[8] = {a0.x, a0.y, a0.z, a0.w, a1.x, a1.y, a1.z, a1.w};
            float b[8] = {b0.x, b0.y, b0.z, b0.w, b1.x, b1.y, b1.z, b1.w};
#pragma unroll
            for (int i = 0; i < 8; i++)
#pragma unroll
                for (int j = 0; j < 8; j++) acc[i][j] += a[i] * b[j];
        }
        __syncthreads();
    }

#pragma unroll
    for (int i = 0; i < 8; i++) {
        int row = m0 + ty * 8 + i;
#pragma unroll
        for (int j = 0; j < 8; j++) {
            C[(size_t)row * EDIM + tx * 8 + j] = sigmoidf_stable(acc[i][j]);
        }
    }
}

// z[512,64] = g_hhead3[head] @ Wd; scatter into stacked output. grid (512, 3)
__global__ void proj3(const float* __restrict__ Wdm,
                      const float* __restrict__ Wds,
                      const float* __restrict__ Wdp,
                      float* __restrict__ out) {
    __shared__ float h[128];
    int head = blockIdx.y;
    const float* Wd = (head == 0) ? Wdm : (head == 1) ? Wds : Wdp;
    int r = blockIdx.x;
    int c = threadIdx.x;
    const float* H = g_hhead3[head];
    h[c]      = H[(size_t)r * EDIM + c];
    h[c + 64] = H[(size_t)r * EDIM + 64 + c];
    __syncthreads();
    float s = 0.f;
#pragma unroll
    for (int k = 0; k < 128; k++) s += h[k] * Wd[k * DDIM + c];
    int set = r >> 8;
    int i = r & 255;
    out[((size_t)(set * 3 + head) * BATCH + i) * DDIM + c] = s;
}

// ---------------------------------------------------------------------------
// Host-side JAX threefry reproduction (partitionable mode)
// ---------------------------------------------------------------------------
namespace tfry {

static inline uint32_t rotl32(uint32_t x, int d) { return (x << d) | (x >> (32 - d)); }

struct Key { uint32_t a, b; };

static Key threefry2x32(Key k, uint32_t x0, uint32_t x1) {
    uint32_t ks0 = k.a, ks1 = k.b, ks2 = k.a ^ k.b ^ 0x1BD11BDAu;
    x0 += ks0; x1 += ks1;
    static const int R0[4] = {13, 15, 26, 6};
    static const int R1[4] = {17, 29, 16, 24};
    auto rounds4 = [&](const int* R) {
        for (int i = 0; i < 4; i++) { x0 += x1; x1 = rotl32(x1, R[i]); x1 ^= x0; }
    };
    rounds4(R0); x0 += ks1; x1 += ks2 + 1u;
    rounds4(R1); x0 += ks2; x1 += ks0 + 2u;
    rounds4(R0); x0 += ks0; x1 += ks1 + 3u;
    rounds4(R1); x0 += ks1; x1 += ks2 + 4u;
    rounds4(R0); x0 += ks2; x1 += ks0 + 5u;
    return Key{x0, x1};
}

static Key fold(Key k, uint32_t i) { return threefry2x32(k, 0u, i); }

static void perm64_prefix(Key key, int n, int* out) {
    Key subkey = fold(key, 1);
    uint32_t bits[64];
    int idx[64];
    for (int i = 0; i < 64; i++) {
        Key r = threefry2x32(subkey, 0u, (uint32_t)i);
        bits[i] = r.a ^ r.b;
        idx[i] = i;
    }
    std::stable_sort(idx, idx + 64,
                     [&](int x, int y) { return bits[x] < bits[y]; });
    for (int j = 0; j < n; j++) out[j] = idx[j];
}

}  // namespace tfry

// ---------------------------------------------------------------------------
// kernel_launch
// ---------------------------------------------------------------------------
extern "C" void kernel_launch(void* const* d_in, const int* in_sizes, int n_in,
                              void* d_out, int out_size) {
    const int*   nodes1  = (const int*)d_in[0];
    const int*   nodes2  = (const int*)d_in[1];
    const int*   nbr_out = (const int*)d_in[2];
    const int*   nbr_in  = (const int*)d_in[3];
    const float* feat    = (const float*)d_in[4];
    const float* W_in    = (const float*)d_in[5];
    const float* W_mean  = (const float*)d_in[6];
    const float* W_std   = (const float*)d_in[7];
    const float* W_pi    = (const float*)d_in[8];
    const float* Wd_mean = (const float*)d_in[11];
    const float* Wd_std  = (const float*)d_in[12];
    const float* Wd_pi   = (const float*)d_in[13];
    float* out = (float*)d_out;

    cudaFuncSetAttribute(fused_l0, cudaFuncAttributeMaxDynamicSharedMemorySize,
                         SMEM_FUSED);

    // --- host threefry: sampling column indices ---
    ColsAll cols;
    tfry::Key root{0u, 42u};
    tfry::Key kset[2] = {tfry::fold(root, 0), tfry::fold(root, 1)};
    for (int set = 0; set < 2; set++) {
        tfry::Key key = kset[set];
        {
            tfry::Key nk = tfry::fold(key, 0);
            tfry::Key p1 = tfry::fold(key, 1);
            tfry::Key p2 = tfry::fold(key, 2);
            tfry::perm64_prefix(p1, NN1, cols.out0[set]);
            tfry::perm64_prefix(p2, NN1, cols.in0[set]);
            key = nk;
        }
        {
            tfry::Key p1 = tfry::fold(key, 1);
            tfry::Key p2 = tfry::fold(key, 2);
            tfry::perm64_prefix(p1, NN0, cols.out1[set]);
            tfry::perm64_prefix(p2, NN0, cols.in1[set]);
        }
    }

    // --- pipeline ---
    build_lvl1<<<(2 * ROWS1 + 255) / 256, 256>>>(nodes1, nodes2, nbr_out, nbr_in, cols);
    build_lvl2<<<(2 * ROWS2 + 255) / 256, 256>>>(nbr_out, nbr_in, cols);

    fused_l0<<<ROWS_BIG / RPB, 256, SMEM_FUSED>>>(feat, W_in);   // -> g_h11

    agg_hop0<<<2 * BATCH, 128>>>(feat, nodes1, nodes2);
    gemm_sig<<<dim3((2 * BATCH) / 128, 1), 256>>>(W_in, nullptr, nullptr, 1); // -> g_h10

    agg_l1<<<2 * BATCH, 128>>>();                                // -> g_aggL1

    gemm_sig<<<dim3((2 * BATCH) / 128, 3), 256>>>(W_mean, W_std, W_pi, 2); // -> g_hhead3
    proj3<<<dim3(2 * BATCH, 3), 64>>>(Wd_mean, Wd_std, Wd_pi, out);
}